// round 16
// baseline (speedup 1.0000x reference)
#include <cuda_runtime.h>
#include <cuda_bf16.h>
#include <cstdint>

// Problem constants: N_VOXELS=80000, C=64, NX=NY=512, B=4
#define NXC    512
#define NYC    512
#define CCH    64
#define BATCHN 4
#define PLANE  (NXC * NYC)            // 262144 spatial slots per batch
#define SLOTS  (BATCHN * PLANE)       // 1048576 total slots
#define PQ     (PLANE / 4)            // 65536 float4-quads per (b,c) plane
#define QTOT   (SLOTS / 4)            // 262144 slot-quads (2^18)
#define KCH    8                      // channels per thread
#define NCG    (CCH / KCH)            // 8 channel groups
#define QPB    64                     // quads per block (2 per thread, 256 thr)

// Per-slot winner: 0 = empty, else (voxel_index + 1).
// Zero-initialized at module load; gather restores all-zeros after reading,
// so "winner == 0 everywhere" holds at every kernel_launch / graph replay.
__device__ int g_winner[SLOTS];
// Zero row for branchless empty-slot loads (never written).
__device__ float4 g_zero4[2];

// ---------------------------------------------------------------------------
// Kernel 1: last-write-wins vote. atomicMax over (voxel_index + 1) => highest
// voxel index wins each slot (deterministic serial-scatter semantics).
// ---------------------------------------------------------------------------
__global__ void vote_kernel(const int* __restrict__ coords, int n) {
    int i = blockIdx.x * blockDim.x + threadIdx.x;
    if (i < n) {
        int b = coords[3 * i + 0];
        int x = coords[3 * i + 1];
        int y = coords[3 * i + 2];
        atomicMax(&g_winner[b * PLANE + x * NYC + y], i + 1);
    }
}

// ---------------------------------------------------------------------------
// Kernel 2: gather + self-reset (R15 structure, unchanged — proven optimum),
// now launched with PDL: blocks spin up and compute their prologue while the
// vote kernel drains; cudaGridDependencySynchronize() gates the first read of
// g_winner (the only vote-dependent data).
//   block = 256 threads = 8 channel-groups x 32 lanes, owning 64 consecutive
//   slot-quads; lane ql processes quads ql (A) and ql+32 (B). MLP=16.
// ---------------------------------------------------------------------------
__global__ void __launch_bounds__(256)
gather_kernel(const float* __restrict__ feat, float* __restrict__ out) {
    __shared__ int4 s_w[QPB];

    unsigned tid   = threadIdx.x;
    unsigned ql    = tid & 31;                  // lane-quad 0..31
    unsigned cg    = tid >> 5;                  // channel group 0..7
    unsigned qbase = blockIdx.x * QPB;

    unsigned qA = qbase + ql;                   // quad A
    unsigned b  = qA >> 16;                     // batch (uniform per block)
    unsigned pq = qA & (PQ - 1);
    unsigned cgo = cg * KCH;
    float4* outq = (float4*)out + (size_t)(b * CCH + cgo) * PQ + pq;

    // Wait for the vote kernel's results before touching g_winner.
    cudaGridDependencySynchronize();

    if (tid < QPB) {
        s_w[tid] = ((const int4*)g_winner)[qbase + tid];
    }
    __syncthreads();
    if (tid < QPB) {
        ((int4*)g_winner)[qbase + tid] = make_int4(0, 0, 0, 0);  // restore invariant
    }

    const int4 wA = s_w[ql];
    const int4 wB = s_w[ql + 32];

    const float4* z = g_zero4;

    // Row pointers for both quads (branchless zero redirect)
    const float4* a0p = (wA.x > 0) ? (const float4*)(feat + (wA.x - 1) * CCH + cgo) : z;
    const float4* a1p = (wA.y > 0) ? (const float4*)(feat + (wA.y - 1) * CCH + cgo) : z;
    const float4* a2p = (wA.z > 0) ? (const float4*)(feat + (wA.z - 1) * CCH + cgo) : z;
    const float4* a3p = (wA.w > 0) ? (const float4*)(feat + (wA.w - 1) * CCH + cgo) : z;
    const float4* b0p = (wB.x > 0) ? (const float4*)(feat + (wB.x - 1) * CCH + cgo) : z;
    const float4* b1p = (wB.y > 0) ? (const float4*)(feat + (wB.y - 1) * CCH + cgo) : z;
    const float4* b2p = (wB.z > 0) ? (const float4*)(feat + (wB.z - 1) * CCH + cgo) : z;
    const float4* b3p = (wB.w > 0) ? (const float4*)(feat + (wB.w - 1) * CCH + cgo) : z;

    // 16 independent loads, all issued before any store (MLP = 16)
    float4 A00 = a0p[0], A01 = a0p[1];
    float4 A10 = a1p[0], A11 = a1p[1];
    float4 A20 = a2p[0], A21 = a2p[1];
    float4 A30 = a3p[0], A31 = a3p[1];
    float4 B00 = b0p[0], B01 = b0p[1];
    float4 B10 = b1p[0], B11 = b1p[1];
    float4 B20 = b2p[0], B21 = b2p[1];
    float4 B30 = b3p[0], B31 = b3p[1];

    // Quad A stores (channels cgo..cgo+7), each a full 512B warp transaction
    __stcs(&outq[0 * PQ], make_float4(A00.x, A10.x, A20.x, A30.x));
    __stcs(&outq[1 * PQ], make_float4(A00.y, A10.y, A20.y, A30.y));
    __stcs(&outq[2 * PQ], make_float4(A00.z, A10.z, A20.z, A30.z));
    __stcs(&outq[3 * PQ], make_float4(A00.w, A10.w, A20.w, A30.w));
    __stcs(&outq[4 * PQ], make_float4(A01.x, A11.x, A21.x, A31.x));
    __stcs(&outq[5 * PQ], make_float4(A01.y, A11.y, A21.y, A31.y));
    __stcs(&outq[6 * PQ], make_float4(A01.z, A11.z, A21.z, A31.z));
    __stcs(&outq[7 * PQ], make_float4(A01.w, A11.w, A21.w, A31.w));

    // Quad B stores: same channels, pq+32 (adjacent 512B range)
    float4* outqB = outq + 32;
    __stcs(&outqB[0 * PQ], make_float4(B00.x, B10.x, B20.x, B30.x));
    __stcs(&outqB[1 * PQ], make_float4(B00.y, B10.y, B20.y, B30.y));
    __stcs(&outqB[2 * PQ], make_float4(B00.z, B10.z, B20.z, B30.z));
    __stcs(&outqB[3 * PQ], make_float4(B00.w, B10.w, B20.w, B30.w));
    __stcs(&outqB[4 * PQ], make_float4(B01.x, B11.x, B21.x, B31.x));
    __stcs(&outqB[5 * PQ], make_float4(B01.y, B11.y, B21.y, B31.y));
    __stcs(&outqB[6 * PQ], make_float4(B01.z, B11.z, B21.z, B31.z));
    __stcs(&outqB[7 * PQ], make_float4(B01.w, B11.w, B21.w, B31.w));
}

// ---------------------------------------------------------------------------
extern "C" void kernel_launch(void* const* d_in, const int* in_sizes, int n_in,
                              void* d_out, int out_size) {
    const float* feat   = (const float*)d_in[0];   // [N, 64] fp32
    const int*   coords = (const int*)d_in[1];     // [N, 3]  int32
    const int n = in_sizes[0] / CCH;               // number of voxels

    vote_kernel<<<(n + 255) / 256, 256>>>(coords, n);

    // Gather launched with programmatic stream serialization (PDL): it may
    // begin dispatch while vote drains; the in-kernel
    // cudaGridDependencySynchronize() enforces the g_winner dependency.
    {
        cudaLaunchConfig_t cfg = {};
        cfg.gridDim  = dim3(QTOT / QPB, 1, 1);     // 4096 blocks
        cfg.blockDim = dim3(256, 1, 1);
        cfg.dynamicSmemBytes = 0;
        cfg.stream = 0;
        cudaLaunchAttribute attr[1];
        attr[0].id = cudaLaunchAttributeProgrammaticStreamSerialization;
        attr[0].val.programmaticStreamSerializationAllowed = 1;
        cfg.attrs = attr;
        cfg.numAttrs = 1;
        cudaLaunchKernelEx(&cfg, gather_kernel, feat, (float*)d_out);
    }
}